// round 4
// baseline (speedup 1.0000x reference)
#include <cuda_runtime.h>

// AccRNNCell: B=512, T=512, F=64, U=512, P=32, L=3
// Persistent batch-parallel kernel, 128 CTAs x 4 batch rows.
// f32x2 packed FMA (FFMA2): thread owns 2 adjacent output columns x 4 rows;
// weight LDG.64 is a natural f32x2 pair, SMEM state is stored DUPLICATED
// ((v,v) pairs) so the activation operand is a natural broadcast LDS.128.

#define UU 512
#define FF 64
#define PP 32
#define NL 3
#define BT 4
#define TPB 256
#define TT 512
#define BB 512

#define SMEM_FLOATS (NL*UU*8 + UU*8 + UU*8 + BT*PP + TPB)
#define SMEM_BYTES  (SMEM_FLOATS * 4)

__device__ __forceinline__ unsigned long long pack2(float x, float y) {
    unsigned long long v;
    asm("mov.b64 %0, {%1, %2};" : "=l"(v) : "f"(x), "f"(y));
    return v;
}
__device__ __forceinline__ void unpack2(unsigned long long v, float& x, float& y) {
    asm("mov.b64 {%0, %1}, %2;" : "=f"(x), "=f"(y) : "l"(v));
}
// store 4 row-values duplicated: (v0,v0,v1,v1,v2,v2,v3,v3)
__device__ __forceinline__ void store_dup(float* dst, float v0, float v1, float v2, float v3) {
    *reinterpret_cast<float4*>(dst)     = make_float4(v0, v0, v1, v1);
    *reinterpret_cast<float4*>(dst + 4) = make_float4(v2, v2, v3, v3);
}

// acc[r] (r=0..3) is an f32x2 pair over (col j0, col j0+1) for batch row r.
// W: weight column base (W + j0), row stride UU. S: duplicated state, 8 floats/k.
template<int K>
__device__ __forceinline__ void gemmK(const float* __restrict__ W,
                                      const float* __restrict__ S,
                                      unsigned long long* __restrict__ a)
{
#pragma unroll 16
    for (int k = 0; k < K; ++k) {
        unsigned long long w = *reinterpret_cast<const unsigned long long*>(W + k * UU);
        ulonglong2 h01 = *reinterpret_cast<const ulonglong2*>(S + k * 8);
        ulonglong2 h23 = *reinterpret_cast<const ulonglong2*>(S + k * 8 + 4);
        asm("fma.rn.f32x2 %0, %1, %2, %0;" : "+l"(a[0]) : "l"(w), "l"(h01.x));
        asm("fma.rn.f32x2 %0, %1, %2, %0;" : "+l"(a[1]) : "l"(w), "l"(h01.y));
        asm("fma.rn.f32x2 %0, %1, %2, %0;" : "+l"(a[2]) : "l"(w), "l"(h23.x));
        asm("fma.rn.f32x2 %0, %1, %2, %0;" : "+l"(a[3]) : "l"(w), "l"(h23.y));
    }
}

__global__ void __launch_bounds__(TPB, 1) accrnn_persistent(
    const float* __restrict__ x,
    const float* __restrict__ WA,  const float* __restrict__ bA,
    const float* __restrict__ WB0, const float* __restrict__ bB0,
    const float* __restrict__ WBr, const float* __restrict__ bBr,
    const float* __restrict__ WC,  const float* __restrict__ bC,
    const float* __restrict__ Wout, const float* __restrict__ bout,
    float* __restrict__ out)
{
    extern __shared__ float smem[];
    float* hsD   = smem;                      // [NL][UU][8] duplicated, 48 KB
    float* prevD = hsD + NL * UU * 8;         // [UU][8] duplicated, 16 KB
    float* nsD   = prevD + UU * 8;            // [UU][8] duplicated, 16 KB
    float* accS  = nsD + UU * 8;              // [BT][PP]
    float* wpart = accS + BT * PP;            // [TPB] split-k partials

    const int tid = threadIdx.x;
    const int b0  = blockIdx.x * BT;
    const int j0  = tid * 2;

    // zero-init recurrent state (fresh every launch -> deterministic)
    for (int i = tid; i < NL * UU * 8; i += TPB) hsD[i] = 0.f;
    if (tid < BT * PP) accS[tid] = 0.f;
    __syncthreads();

    const int xr = tid >> 6;            // 0..3  (BT*FF == TPB)
    const int xf = tid & 63;            // 0..63
    const float* xrow = x + ((size_t)(b0 + xr) * TT) * FF + xf;

    for (int t = 0; t < TT; ++t) {
        // ---- prevD = concat(x_t, acc), duplicated ----
        {
            float v = xrow[(size_t)t * FF];
            *reinterpret_cast<float2*>(&prevD[xf * 8 + 2 * xr]) = make_float2(v, v);
        }
        if (tid < BT * PP) {
            int r = tid >> 5, p = tid & 31;
            float v = accS[tid];
            *reinterpret_cast<float2*>(&prevD[(FF + p) * 8 + 2 * r]) = make_float2(v, v);
        }
        __syncthreads();

        #pragma unroll
        for (int l = 0; l < NL; ++l) {
            const float* Wa = WA + (size_t)l * UU * UU + j0;
            const float* Wb = (l == 0) ? (WB0 + j0)
                                       : (WBr + (size_t)(l - 1) * UU * UU + j0);

            float bv0 = bA[l * UU + j0]     + ((l == 0) ? bB0[j0]     : bBr[(l - 1) * UU + j0]);
            float bv1 = bA[l * UU + j0 + 1] + ((l == 0) ? bB0[j0 + 1] : bBr[(l - 1) * UU + j0 + 1]);

            unsigned long long a[4];
            a[0] = a[1] = a[2] = a[3] = pack2(bv0, bv1);

            gemmK<UU>(Wa, hsD + l * UU * 8, a);          // latent_state = hs[l] @ WA[l]
            if (l == 0) gemmK<FF + PP>(Wb, prevD, a);    // latent_input = prev @ WB
            else        gemmK<UU>(Wb, prevD, a);

            float n00, n10, n01, n11, n02, n12, n03, n13;
            unpack2(a[0], n00, n10); unpack2(a[1], n01, n11);
            unpack2(a[2], n02, n12); unpack2(a[3], n03, n13);
            store_dup(nsD + j0 * 8,       n00, n01, n02, n03);
            store_dup(nsD + (j0 + 1) * 8, n10, n11, n12, n13);
            __syncthreads();   // nsD complete; old prevD / hsD[l] fully consumed

            // prev' = new_state @ WC[l] + bC[l]
            const float* Wc = WC + (size_t)l * UU * UU + j0;
            unsigned long long c[4];
            c[0] = c[1] = c[2] = c[3] = pack2(bC[l * UU + j0], bC[l * UU + j0 + 1]);
            gemmK<UU>(Wc, nsD, c);

            // commit hidden state from registers; overwrite prevD
            store_dup(hsD + (l * UU + j0) * 8,       n00, n01, n02, n03);
            store_dup(hsD + (l * UU + j0 + 1) * 8,   n10, n11, n12, n13);
            float c00, c10, c01, c11, c02, c12, c03, c13;
            unpack2(c[0], c00, c10); unpack2(c[1], c01, c11);
            unpack2(c[2], c02, c12); unpack2(c[3], c03, c13);
            store_dup(prevD + j0 * 8,       c00, c01, c02, c03);
            store_dup(prevD + (j0 + 1) * 8, c10, c11, c12, c13);
            __syncthreads();
        }

        // ---- res = prev @ Wout + bout ; acc += res ; emit ----
        {
            int ks = tid >> 7;           // split-k: 0 or 1
            int rp = tid & 127;
            int r = rp >> 5, p = rp & 31;
            float s = (ks == 0) ? bout[p] : 0.f;
            int kbeg = ks * (UU / 2);
            #pragma unroll 8
            for (int k = kbeg; k < kbeg + UU / 2; ++k)
                s = fmaf(prevD[k * 8 + 2 * r], Wout[k * PP + p], s);
            wpart[tid] = s;
        }
        __syncthreads();
        if (tid < BT * PP) {
            int r = tid >> 5, p = tid & 31;
            float tot = wpart[tid] + wpart[tid + 128];
            accS[tid] += tot;
            out[((size_t)(b0 + r) * TT + t) * PP + p] = tot;
        }
        __syncthreads();
    }
}

extern "C" void kernel_launch(void* const* d_in, const int* in_sizes, int n_in,
                              void* d_out, int out_size)
{
    const float* x    = (const float*)d_in[0];
    const float* WA   = (const float*)d_in[1];
    const float* bA   = (const float*)d_in[2];
    const float* WB0  = (const float*)d_in[3];
    const float* bB0  = (const float*)d_in[4];
    const float* WBr  = (const float*)d_in[5];
    const float* bBr  = (const float*)d_in[6];
    const float* WC   = (const float*)d_in[7];
    const float* bC   = (const float*)d_in[8];
    const float* Wout = (const float*)d_in[9];
    const float* bout = (const float*)d_in[10];
    float* out = (float*)d_out;

    cudaFuncSetAttribute(accrnn_persistent,
                         cudaFuncAttributeMaxDynamicSharedMemorySize, SMEM_BYTES);
    accrnn_persistent<<<BB / BT, TPB, SMEM_BYTES>>>(x, WA, bA, WB0, bB0, WBr, bBr,
                                                    WC, bC, Wout, bout, out);
}

// round 5
// speedup vs baseline: 1.1432x; 1.1432x over previous
#include <cuda_runtime.h>

// AccRNNCell: B=512, T=512, F=64, U=512, P=32, L=3
// Persistent batch-parallel kernel, 128 CTAs x 4 batch rows, 256 threads.
// Row-pair f32x2: 128 col-threads own 4 cols x 4 rows (16 MACs/k), x2 k-split
// groups. Activations read as natural (r0,r1),(r2,r3) u64 pairs from SMEM
// (broadcast, 1 wavefront/warp); weights LDG.128 (4 cols) duplicated into
// lanes via register MOVs. Minimizes L1tex wavefronts per MAC.

#define UU 512
#define FF 64
#define PP 32
#define NL 3
#define BT 4
#define TPB 256
#define TT 512
#define BB 512

typedef unsigned long long u64;

// hsT[NL][UU][BT] + prevT[UU][BT] + nsT[UU][BT] + part[2][UU][BT] + accS + wpart
#define SMEM_FLOATS (NL*UU*BT + UU*BT + UU*BT + 2*UU*BT + BT*PP + TPB)
#define SMEM_BYTES  (SMEM_FLOATS * 4)

__device__ __forceinline__ u64 pack2(float x, float y) {
    u64 v; asm("mov.b64 %0, {%1, %2};" : "=l"(v) : "f"(x), "f"(y)); return v;
}

// acc layout: a[2c+h] = f32x2 over rows (2h, 2h+1) for column j0+c.
template<int K>
__device__ __forceinline__ void gemm_rp(const float* __restrict__ W,   // + j0
                                        const float* __restrict__ S,   // [k][BT]
                                        u64* __restrict__ a)
{
#pragma unroll 8
    for (int k = 0; k < K; ++k) {
        float4 w = __ldg(reinterpret_cast<const float4*>(W + (size_t)k * UU));
        ulonglong2 h = *reinterpret_cast<const ulonglong2*>(S + k * BT);
        u64 w0 = pack2(w.x, w.x), w1 = pack2(w.y, w.y);
        u64 w2 = pack2(w.z, w.z), w3 = pack2(w.w, w.w);
        asm("fma.rn.f32x2 %0, %1, %2, %0;" : "+l"(a[0]) : "l"(w0), "l"(h.x));
        asm("fma.rn.f32x2 %0, %1, %2, %0;" : "+l"(a[1]) : "l"(w0), "l"(h.y));
        asm("fma.rn.f32x2 %0, %1, %2, %0;" : "+l"(a[2]) : "l"(w1), "l"(h.x));
        asm("fma.rn.f32x2 %0, %1, %2, %0;" : "+l"(a[3]) : "l"(w1), "l"(h.y));
        asm("fma.rn.f32x2 %0, %1, %2, %0;" : "+l"(a[4]) : "l"(w2), "l"(h.x));
        asm("fma.rn.f32x2 %0, %1, %2, %0;" : "+l"(a[5]) : "l"(w2), "l"(h.y));
        asm("fma.rn.f32x2 %0, %1, %2, %0;" : "+l"(a[6]) : "l"(w3), "l"(h.x));
        asm("fma.rn.f32x2 %0, %1, %2, %0;" : "+l"(a[7]) : "l"(w3), "l"(h.y));
    }
}

__device__ __forceinline__ void store_part(float* __restrict__ pp, const u64* __restrict__ a) {
#pragma unroll
    for (int c = 0; c < 4; ++c) {
        ulonglong2 v; v.x = a[2 * c]; v.y = a[2 * c + 1];
        *reinterpret_cast<ulonglong2*>(pp + c * BT) = v;
    }
}

__device__ __forceinline__ float4 f4add(float4 a, float4 b) {
    return make_float4(a.x + b.x, a.y + b.y, a.z + b.z, a.w + b.w);
}

__global__ void __launch_bounds__(TPB, 1) accrnn_persistent(
    const float* __restrict__ x,
    const float* __restrict__ WA,  const float* __restrict__ bA,
    const float* __restrict__ WB0, const float* __restrict__ bB0,
    const float* __restrict__ WBr, const float* __restrict__ bBr,
    const float* __restrict__ WC,  const float* __restrict__ bC,
    const float* __restrict__ Wout, const float* __restrict__ bout,
    float* __restrict__ out)
{
    extern __shared__ float smem[];
    float* hsT   = smem;                       // [NL][UU][BT]
    float* prevT = hsT + NL * UU * BT;         // [UU][BT]
    float* nsT   = prevT + UU * BT;            // [UU][BT]
    float* part  = nsT + UU * BT;              // [2][UU][BT]
    float* accS  = part + 2 * UU * BT;         // [BT*PP]
    float* wpart = accS + BT * PP;             // [TPB]

    const int tid = threadIdx.x;
    const int b0  = blockIdx.x * BT;
    const int grp = tid >> 7;          // k-split / operand group (0 or 1)
    const int ct  = tid & 127;         // col-thread within group
    const int j0  = ct * 4;            // 4 owned columns

    for (int i = tid; i < NL * UU * BT; i += TPB) hsT[i] = 0.f;
    if (tid < BT * PP) accS[tid] = 0.f;
    __syncthreads();

    const int xr = tid >> 6;           // 0..3
    const int xf = tid & 63;           // 0..63
    const float* xrow = x + ((size_t)(b0 + xr) * TT) * FF + xf;

    for (int t = 0; t < TT; ++t) {
        // ---- prevT = concat(x_t, acc) ----
        prevT[xf * BT + xr] = xrow[(size_t)t * FF];
        if (tid < BT * PP) {
            int r = tid >> 5, p = tid & 31;
            prevT[(FF + p) * BT + r] = accS[tid];
        }
        __syncthreads();

        #pragma unroll
        for (int l = 0; l < NL; ++l) {
            // ---- stage 1: ns = hs[l]@WA[l] (grp0) + prev@WB (grp1) + biases ----
            u64 a[8];
            if (grp == 0) {
                #pragma unroll
                for (int c = 0; c < 4; ++c) {
                    float b = bA[l * UU + j0 + c] +
                              ((l == 0) ? bB0[j0 + c] : bBr[(l - 1) * UU + j0 + c]);
                    a[2 * c] = a[2 * c + 1] = pack2(b, b);
                }
                gemm_rp<UU>(WA + (size_t)l * UU * UU + j0, hsT + l * UU * BT, a);
            } else {
                #pragma unroll
                for (int i = 0; i < 8; ++i) a[i] = 0ull;
                if (l == 0) gemm_rp<FF + PP>(WB0 + j0, prevT, a);
                else        gemm_rp<UU>(WBr + (size_t)(l - 1) * UU * UU + j0, prevT, a);
            }
            store_part(part + grp * UU * BT + j0 * BT, a);
            __syncthreads();
            {   // combine: 2 cols per thread -> nsT and hsT[l]
                int col = tid * 2;
                float4 s0 = f4add(*reinterpret_cast<float4*>(part + col * BT),
                                  *reinterpret_cast<float4*>(part + UU * BT + col * BT));
                float4 s1 = f4add(*reinterpret_cast<float4*>(part + (col + 1) * BT),
                                  *reinterpret_cast<float4*>(part + UU * BT + (col + 1) * BT));
                *reinterpret_cast<float4*>(nsT + col * BT)       = s0;
                *reinterpret_cast<float4*>(nsT + (col + 1) * BT) = s1;
                *reinterpret_cast<float4*>(hsT + l * UU * BT + col * BT)       = s0;
                *reinterpret_cast<float4*>(hsT + l * UU * BT + (col + 1) * BT) = s1;
            }
            __syncthreads();

            // ---- stage 2: prev' = ns @ WC[l] + bC[l], split-k halves ----
            u64 c[8];
            if (grp == 0) {
                #pragma unroll
                for (int cc = 0; cc < 4; ++cc) {
                    float b = bC[l * UU + j0 + cc];
                    c[2 * cc] = c[2 * cc + 1] = pack2(b, b);
                }
            } else {
                #pragma unroll
                for (int i = 0; i < 8; ++i) c[i] = 0ull;
            }
            gemm_rp<UU / 2>(WC + (size_t)l * UU * UU + (size_t)(grp * (UU / 2)) * UU + j0,
                            nsT + grp * (UU / 2) * BT, c);
            store_part(part + grp * UU * BT + j0 * BT, c);
            __syncthreads();
            {   // combine -> prevT
                int col = tid * 2;
                float4 s0 = f4add(*reinterpret_cast<float4*>(part + col * BT),
                                  *reinterpret_cast<float4*>(part + UU * BT + col * BT));
                float4 s1 = f4add(*reinterpret_cast<float4*>(part + (col + 1) * BT),
                                  *reinterpret_cast<float4*>(part + UU * BT + (col + 1) * BT));
                *reinterpret_cast<float4*>(prevT + col * BT)       = s0;
                *reinterpret_cast<float4*>(prevT + (col + 1) * BT) = s1;
            }
            __syncthreads();
        }

        // ---- res = prev @ Wout + bout ; acc += res ; emit ----
        {
            int rp = tid & 127;
            int r = rp >> 5, p = rp & 31;
            float s = (grp == 0) ? bout[p] : 0.f;
            int kbeg = grp * (UU / 2);
            #pragma unroll 8
            for (int k = kbeg; k < kbeg + UU / 2; ++k)
                s = fmaf(prevT[k * BT + r], Wout[k * PP + p], s);
            wpart[tid] = s;
        }
        __syncthreads();
        if (tid < BT * PP) {
            int r = tid >> 5, p = tid & 31;
            float tot = wpart[tid] + wpart[tid + 128];
            accS[tid] += tot;
            out[((size_t)(b0 + r) * TT + t) * PP + p] = tot;
        }
        __syncthreads();
    }
}

extern "C" void kernel_launch(void* const* d_in, const int* in_sizes, int n_in,
                              void* d_out, int out_size)
{
    const float* x    = (const float*)d_in[0];
    const float* WA   = (const float*)d_in[1];
    const float* bA   = (const float*)d_in[2];
    const float* WB0  = (const float*)d_in[3];
    const float* bB0  = (const float*)d_in[4];
    const float* WBr  = (const float*)d_in[5];
    const float* bBr  = (const float*)d_in[6];
    const float* WC   = (const float*)d_in[7];
    const float* bC   = (const float*)d_in[8];
    const float* Wout = (const float*)d_in[9];
    const float* bout = (const float*)d_in[10];
    float* out = (float*)d_out;

    cudaFuncSetAttribute(accrnn_persistent,
                         cudaFuncAttributeMaxDynamicSharedMemorySize, SMEM_BYTES);
    accrnn_persistent<<<BB / BT, TPB, SMEM_BYTES>>>(x, WA, bA, WB0, bB0, WBr, bBr,
                                                    WC, bC, Wout, bout, out);
}

// round 6
// speedup vs baseline: 1.6278x; 1.4239x over previous
#include <cuda_runtime.h>

// AccRNNCell: B=512, T=512, F=64, U=512, P=32, L=3
// Persistent batch-parallel kernel, 128 CTAs x 4 batch rows, 512 threads.
// 4 k-split groups x 128 col-threads; each thread owns 4 cols x 4 rows
// (16 MACs/k via 8 FFMA2). 16 warps/CTA for L2-latency hiding.

#define UU 512
#define FF 64
#define PP 32
#define NL 3
#define BT 4
#define TPB 512
#define NG 4              // k-split groups
#define TT 512
#define BB 512

typedef unsigned long long u64;

// hsT + prevT + nsT + part[NG] + accS + wpart
#define SMEM_FLOATS (NL*UU*BT + UU*BT + UU*BT + NG*UU*BT + BT*PP + TPB)
#define SMEM_BYTES  (SMEM_FLOATS * 4)

__device__ __forceinline__ u64 pack2(float x, float y) {
    u64 v; asm("mov.b64 %0, {%1, %2};" : "=l"(v) : "f"(x), "f"(y)); return v;
}

// a[2c+h] = f32x2 over rows (2h,2h+1) for column j0+c.
template<int K>
__device__ __forceinline__ void gemm_rp(const float* __restrict__ W,   // + kbeg*UU + j0
                                        const float* __restrict__ S,   // + kbeg*BT
                                        u64* __restrict__ a)
{
#pragma unroll 8
    for (int k = 0; k < K; ++k) {
        float4 w = __ldg(reinterpret_cast<const float4*>(W + (size_t)k * UU));
        ulonglong2 h = *reinterpret_cast<const ulonglong2*>(S + k * BT);
        u64 w0 = pack2(w.x, w.x), w1 = pack2(w.y, w.y);
        u64 w2 = pack2(w.z, w.z), w3 = pack2(w.w, w.w);
        asm("fma.rn.f32x2 %0, %1, %2, %0;" : "+l"(a[0]) : "l"(w0), "l"(h.x));
        asm("fma.rn.f32x2 %0, %1, %2, %0;" : "+l"(a[1]) : "l"(w0), "l"(h.y));
        asm("fma.rn.f32x2 %0, %1, %2, %0;" : "+l"(a[2]) : "l"(w1), "l"(h.x));
        asm("fma.rn.f32x2 %0, %1, %2, %0;" : "+l"(a[3]) : "l"(w1), "l"(h.y));
        asm("fma.rn.f32x2 %0, %1, %2, %0;" : "+l"(a[4]) : "l"(w2), "l"(h.x));
        asm("fma.rn.f32x2 %0, %1, %2, %0;" : "+l"(a[5]) : "l"(w2), "l"(h.y));
        asm("fma.rn.f32x2 %0, %1, %2, %0;" : "+l"(a[6]) : "l"(w3), "l"(h.x));
        asm("fma.rn.f32x2 %0, %1, %2, %0;" : "+l"(a[7]) : "l"(w3), "l"(h.y));
    }
}

__device__ __forceinline__ void store_part(float* __restrict__ pp, const u64* __restrict__ a) {
#pragma unroll
    for (int c = 0; c < 4; ++c) {
        ulonglong2 v; v.x = a[2 * c]; v.y = a[2 * c + 1];
        *reinterpret_cast<ulonglong2*>(pp + c * BT) = v;
    }
}

__global__ void __launch_bounds__(TPB, 1) accrnn_persistent(
    const float* __restrict__ x,
    const float* __restrict__ WA,  const float* __restrict__ bA,
    const float* __restrict__ WB0, const float* __restrict__ bB0,
    const float* __restrict__ WBr, const float* __restrict__ bBr,
    const float* __restrict__ WC,  const float* __restrict__ bC,
    const float* __restrict__ Wout, const float* __restrict__ bout,
    float* __restrict__ out)
{
    extern __shared__ float smem[];
    float* hsT   = smem;                       // [NL][UU][BT]
    float* prevT = hsT + NL * UU * BT;         // [UU][BT]
    float* nsT   = prevT + UU * BT;            // [UU][BT]
    float* part  = nsT + UU * BT;              // [NG][UU][BT]
    float* accS  = part + NG * UU * BT;        // [BT*PP]
    float* wpart = accS + BT * PP;             // [TPB]

    const int tid = threadIdx.x;
    const int b0  = blockIdx.x * BT;
    const int grp = tid >> 7;          // 0..3
    const int ct  = tid & 127;
    const int j0  = ct * 4;

    for (int i = tid; i < NL * UU * BT; i += TPB) hsT[i] = 0.f;
    if (tid < BT * PP) accS[tid] = 0.f;
    __syncthreads();

    const int xr = (tid >> 6) & 3;
    const int xf = tid & 63;
    const float* xrow = x + ((size_t)(b0 + xr) * TT) * FF + xf;

    for (int t = 0; t < TT; ++t) {
        // ---- prevT = concat(x_t, acc) ----
        if (tid < BT * FF) prevT[xf * BT + xr] = xrow[(size_t)t * FF];
        if (tid < BT * PP) {
            int r = tid >> 5, p = tid & 31;
            prevT[(FF + p) * BT + r] = accS[tid];
        }
        __syncthreads();

        #pragma unroll
        for (int l = 0; l < NL; ++l) {
            // ---- stage 1: ns = hs[l]@WA[l] (grp0/1) + prev@WB (grp2/3) ----
            u64 a[8];
            if (grp == 0) {
                #pragma unroll
                for (int c = 0; c < 4; ++c) {
                    float b = bA[l * UU + j0 + c] +
                              ((l == 0) ? bB0[j0 + c] : bBr[(l - 1) * UU + j0 + c]);
                    a[2 * c] = a[2 * c + 1] = pack2(b, b);
                }
            } else {
                #pragma unroll
                for (int i = 0; i < 8; ++i) a[i] = 0ull;
            }
            if (grp < 2) {
                const float* Wa = WA + (size_t)l * UU * UU + j0;
                int kbeg = grp * (UU / 2);
                gemm_rp<UU / 2>(Wa + (size_t)kbeg * UU, hsT + l * UU * BT + kbeg * BT, a);
            } else if (l == 0) {
                int kbeg = (grp - 2) * ((FF + PP) / 2);
                gemm_rp<(FF + PP) / 2>(WB0 + j0 + (size_t)kbeg * UU, prevT + kbeg * BT, a);
            } else {
                const float* Wb = WBr + (size_t)(l - 1) * UU * UU + j0;
                int kbeg = (grp - 2) * (UU / 2);
                gemm_rp<UU / 2>(Wb + (size_t)kbeg * UU, prevT + kbeg * BT, a);
            }
            store_part(part + grp * UU * BT + j0 * BT, a);
            __syncthreads();
            {   // combine: 1 col per thread -> nsT and hsT[l]
                int col = tid;
                float4 s = *reinterpret_cast<float4*>(part + col * BT);
                #pragma unroll
                for (int g = 1; g < NG; ++g) {
                    float4 q = *reinterpret_cast<float4*>(part + g * UU * BT + col * BT);
                    s.x += q.x; s.y += q.y; s.z += q.z; s.w += q.w;
                }
                *reinterpret_cast<float4*>(nsT + col * BT) = s;
                *reinterpret_cast<float4*>(hsT + l * UU * BT + col * BT) = s;
            }
            __syncthreads();

            // ---- stage 2: prev' = ns @ WC[l] + bC[l], 4-way k-split ----
            u64 c[8];
            if (grp == 0) {
                #pragma unroll
                for (int cc = 0; cc < 4; ++cc) {
                    float b = bC[l * UU + j0 + cc];
                    c[2 * cc] = c[2 * cc + 1] = pack2(b, b);
                }
            } else {
                #pragma unroll
                for (int i = 0; i < 8; ++i) c[i] = 0ull;
            }
            {
                int kbeg = grp * (UU / NG);
                gemm_rp<UU / NG>(WC + (size_t)l * UU * UU + (size_t)kbeg * UU + j0,
                                 nsT + kbeg * BT, c);
            }
            store_part(part + grp * UU * BT + j0 * BT, c);
            __syncthreads();
            {   // combine -> prevT
                int col = tid;
                float4 s = *reinterpret_cast<float4*>(part + col * BT);
                #pragma unroll
                for (int g = 1; g < NG; ++g) {
                    float4 q = *reinterpret_cast<float4*>(part + g * UU * BT + col * BT);
                    s.x += q.x; s.y += q.y; s.z += q.z; s.w += q.w;
                }
                *reinterpret_cast<float4*>(prevT + col * BT) = s;
            }
            __syncthreads();
        }

        // ---- res = prev @ Wout + bout ; acc += res ; emit ----
        {
            int rp = tid & 127;
            int r = rp >> 5, p = rp & 31;
            float s = (grp == 0) ? bout[p] : 0.f;
            int kbeg = grp * (UU / NG);
            #pragma unroll 8
            for (int k = kbeg; k < kbeg + UU / NG; ++k)
                s = fmaf(prevT[k * BT + r], Wout[k * PP + p], s);
            wpart[tid] = s;
        }
        __syncthreads();
        if (tid < BT * PP) {
            int r = tid >> 5, p = tid & 31;
            float tot = wpart[tid] + wpart[tid + 128] + wpart[tid + 256] + wpart[tid + 384];
            accS[tid] += tot;
            out[((size_t)(b0 + r) * TT + t) * PP + p] = tot;
        }
        __syncthreads();
    }
}

extern "C" void kernel_launch(void* const* d_in, const int* in_sizes, int n_in,
                              void* d_out, int out_size)
{
    const float* x    = (const float*)d_in[0];
    const float* WA   = (const float*)d_in[1];
    const float* bA   = (const float*)d_in[2];
    const float* WB0  = (const float*)d_in[3];
    const float* bB0  = (const float*)d_in[4];
    const float* WBr  = (const float*)d_in[5];
    const float* bBr  = (const float*)d_in[6];
    const float* WC   = (const float*)d_in[7];
    const float* bC   = (const float*)d_in[8];
    const float* Wout = (const float*)d_in[9];
    const float* bout = (const float*)d_in[10];
    float* out = (float*)d_out;

    cudaFuncSetAttribute(accrnn_persistent,
                         cudaFuncAttributeMaxDynamicSharedMemorySize, SMEM_BYTES);
    accrnn_persistent<<<BB / BT, TPB, SMEM_BYTES>>>(x, WA, bA, WB0, bB0, WBr, bBr,
                                                    WC, bC, Wout, bout, out);
}